// round 11
// baseline (speedup 1.0000x reference)
#include <cuda_runtime.h>
#include <cstdint>

#define SEQ 2048
#define NB  64
#define ID  256
#define HD  256
#define G3  768
#define SW  264            // Ws row stride in floats
#define NGRU 64
#define NPROD 84
#define NCTA (NGRU + NPROD)
#define SMEM_BYTES (2 * 96 * SW * 4)   // 202752 bytes

using u64 = unsigned long long;

// ---------------------------------------------------------------- f32x2 helpers
__device__ __forceinline__ u64 ffma2(u64 a, u64 b, u64 c) {
    u64 d; asm("fma.rn.f32x2 %0, %1, %2, %3;" : "=l"(d) : "l"(a), "l"(b), "l"(c)); return d;
}
__device__ __forceinline__ u64 fmul2(u64 a, u64 b) {
    u64 d; asm("mul.rn.f32x2 %0, %1, %2;" : "=l"(d) : "l"(a), "l"(b)); return d;
}
__device__ __forceinline__ u64 pack2(float lo, float hi) {
    u64 d; asm("mov.b64 %0, {%1, %2};" : "=l"(d) : "f"(lo), "f"(hi)); return d;
}
__device__ __forceinline__ float2 unpack2(u64 v) {
    float2 r; asm("mov.b64 {%0, %1}, %2;" : "=f"(r.x), "=f"(r.y) : "l"(v)); return r;
}

// ---------------------------------------------------------------- sync helpers
__device__ __forceinline__ void redAddRelease(unsigned* p, unsigned v) {
    asm volatile("red.add.release.gpu.global.u32 [%0], %1;" :: "l"(p), "r"(v) : "memory");
}
__device__ __forceinline__ unsigned ldAcquire(const unsigned* p) {
    unsigned v; asm volatile("ld.acquire.gpu.global.u32 %0, [%1];" : "=r"(v) : "l"(p) : "memory"); return v;
}

__device__ __forceinline__ float pick4(float4 v, int r) {
    float lo = (r & 1) ? v.y : v.x;
    float hi = (r & 1) ? v.w : v.z;
    return (r & 2) ? hi : lo;
}

__device__ __forceinline__ float sigmoidf_(float x) { return 1.f / (1.f + __expf(-x)); }
__device__ __forceinline__ float tanhf_(float x) {
    float e = __expf(2.f * x);
    return 1.f - 2.f / (e + 1.f);
}

// 805 MB scratch: [dir][t][gate(768)][b(64)]
__device__ float g_gx[(size_t)2 * SEQ * G3 * NB];
// double-buffered hidden state: [dir][parity][b*HD]
__device__ float g_h[2][2][NB * HD];
// h barriers: [dir(2)][rowgrp(8)] monotonic counters (64 warp arrivals/step), 128B apart
__device__ unsigned g_bar[16 * 32];
// gx slot counters: slot q = step*2 + dir; ready when == 12
__device__ unsigned g_cnt[2 * SEQ];

// ---------------------------------------------------------------- init
__global__ void init_kernel() {
    int tid = blockIdx.x * blockDim.x + threadIdx.x;
    int nthr = blockDim.x * gridDim.x;
    float* p = &g_h[0][0][0];
    for (int i = tid; i < 2 * 2 * NB * HD; i += nthr) p[i] = 0.f;
    for (int i = tid; i < 2 * SEQ; i += nthr) g_cnt[i] = 0u;
    for (int i = tid; i < 16 * 32; i += nthr) g_bar[i] = 0u;
}

// ---------------------------------------------------------------- producer role: one gx tile
__device__ void gx_tile(
    float* sp, int dir, int t, int n0,
    const float* __restrict__ X,
    const float* __restrict__ W, const float* __restrict__ bias)
{
    float* As = sp;              // [16][68]
    float* Bs = sp + 1088;       // [16][68]
    float* Cs = sp + 2176;       // [64][68]

    const int tid = threadIdx.x;
    const int ty = tid >> 4, tx = tid & 15;
    const int lr = tid >> 2, lc = (tid & 3) << 2;

    const float* Ab  = X + (size_t)t * (NB * ID) + (size_t)lr * ID + lc;
    const float* Bb2 = W + (size_t)(n0 + lr) * ID + lc;

    u64 acc2[4][2];
#pragma unroll
    for (int i = 0; i < 4; i++) { acc2[i][0] = 0ull; acc2[i][1] = 0ull; }

    for (int k0 = 0; k0 < ID; k0 += 16) {
        float4 a4 = *(const float4*)(Ab + k0);
        float4 b4 = *(const float4*)(Bb2 + k0);
        As[(lc + 0) * 68 + lr] = a4.x; As[(lc + 1) * 68 + lr] = a4.y;
        As[(lc + 2) * 68 + lr] = a4.z; As[(lc + 3) * 68 + lr] = a4.w;
        Bs[(lc + 0) * 68 + lr] = b4.x; Bs[(lc + 1) * 68 + lr] = b4.y;
        Bs[(lc + 2) * 68 + lr] = b4.z; Bs[(lc + 3) * 68 + lr] = b4.w;
        __syncthreads();
#pragma unroll
        for (int k = 0; k < 16; k++) {
            float4 av = *(const float4*)&As[k * 68 + (ty << 2)];
            float4 bv = *(const float4*)&Bs[k * 68 + (tx << 2)];
            const u64 b01 = pack2(bv.x, bv.y);
            const u64 b23 = pack2(bv.z, bv.w);
            float ar[4] = {av.x, av.y, av.z, av.w};
#pragma unroll
            for (int r = 0; r < 4; r++) {
                const u64 aa = pack2(ar[r], ar[r]);
                acc2[r][0] = ffma2(aa, b01, acc2[r][0]);
                acc2[r][1] = ffma2(aa, b23, acc2[r][1]);
            }
        }
        __syncthreads();
    }

#pragma unroll
    for (int r = 0; r < 4; r++) {
        float2 c01 = unpack2(acc2[r][0]);
        float2 c23 = unpack2(acc2[r][1]);
        float cc[4] = {c01.x, c01.y, c23.x, c23.y};
#pragma unroll
        for (int c = 0; c < 4; c++)
            Cs[((tx << 2) + c) * 68 + (ty << 2) + r] = cc[c] + __ldg(bias + n0 + (tx << 2) + c);
    }
    __syncthreads();

    float* dst = g_gx + ((size_t)dir * SEQ + t) * ((size_t)G3 * NB) + (size_t)n0 * NB;
#pragma unroll
    for (int i = 0; i < 4; i++) {
        int g  = (tid >> 4) + (i << 4);
        int b4 = (tid & 15) << 2;
        float4 v = *(const float4*)&Cs[g * 68 + b4];
        __stcg((float4*)(dst + g * NB + b4), v);
    }
    __syncthreads();   // all stores done before tid0 releases the slot
}

// ---------------------------------------------------------------- fused persistent kernel
__global__ __launch_bounds__(256, 1) void fused_kernel(
    const float* __restrict__ X,
    const int*   __restrict__ D,
    const float* __restrict__ Wihf, const float* __restrict__ Whf,
    const float* __restrict__ bif,  const float* __restrict__ bhf,
    const float* __restrict__ Wihb, const float* __restrict__ Whb,
    const float* __restrict__ bib,  const float* __restrict__ bhb,
    float* __restrict__ out)
{
    extern __shared__ __align__(16) float sp[];
    const int tid = threadIdx.x;

    if (blockIdx.x >= NGRU) {
        // ================= producer role: gx tiles in consumption-priority order
        const int w = blockIdx.x - NGRU;
        for (int j = w; j < 2 * SEQ * 12; j += NPROD) {
            const int q   = j / 12;
            const int n0  = (j - q * 12) << 6;
            const int dir = q & 1;
            const int st  = q >> 1;
            const int t   = dir ? (SEQ - 1 - st) : st;
            if (dir) gx_tile(sp, 1, t, n0, X, Wihb, bib);
            else     gx_tile(sp, 0, t, n0, X, Wihf, bif);
            if (tid == 0) redAddRelease(&g_cnt[q], 1u);
        }
        return;
    }

    // ================= gru role: 8 rows x 32 hcols per CTA, both dirs, 2 phases/step
    const int cid    = blockIdx.x;
    const int rowgrp = cid >> 3;          // 0..7  (8 batch rows each)
    const int hcgrp  = cid & 7;           // 0..7  (32 hcols each)
    const int hc0    = hcgrp * 32;
    unsigned* barp[2] = { &g_bar[(0 * 8 + rowgrp) * 32], &g_bar[(1 * 8 + rowgrp) * 32] };

    float* Ws = sp;   // [dir][96 rows = 3 gates x 32 hl][SW]
    for (int idx = tid; idx < 2 * 96 * 256; idx += 256) {
        int d = idx / (96 * 256);
        int r = (idx >> 8) % 96, k = idx & 255;
        int g = r >> 5, hl = r & 31;
        const float* Whh = d ? Whb : Whf;
        Ws[(d * 96 + r) * SW + k] = Whh[(size_t)(g * 256 + hc0 + hl) * HD + k];
    }

    const int lane = tid & 31;
    const int kc   = tid & 15;            // 0..15
    const int bl2  = (tid >> 4) & 1;      // 0..1
    const int jg   = tid >> 5;            // 0..7 (hcol quad)
    const int myq  = kc & 3;
    const int myrb = kc >> 2;
    const int rowbase = rowgrp * 8 + bl2 * 4;
    const int b_own   = rowbase + myrb;
    const int hcol    = hc0 + jg * 4 + myq;

    float bR[2], bZ[2], bN[2];
#pragma unroll
    for (int d = 0; d < 2; d++) {
        const float* bhh = d ? bhb : bhf;
        bR[d] = __ldg(bhh + hcol);
        bZ[d] = __ldg(bhh + 256 + hcol);
        bN[d] = __ldg(bhh + 512 + hcol);
    }

    __syncthreads();   // Ws ready

    float my_h[2] = {0.f, 0.f};
    float pf_gxr[2], pf_gxz[2], pf_gxn[2];
    int4  pf_md[2];

    // wait for step-0 slots of both dirs (lane0 poll + syncwarp), then prefetch
    if (lane == 0) {
        while (ldAcquire(&g_cnt[0]) < 12u) { }
        while (ldAcquire(&g_cnt[1]) < 12u) { }
    }
    __syncwarp();
#pragma unroll
    for (int d = 0; d < 2; d++) {
        const int t0 = d ? (SEQ - 1) : 0;
        const float* gx = g_gx + ((size_t)d * SEQ + t0) * ((size_t)G3 * NB);
        pf_gxr[d] = __ldcg(gx + (size_t)hcol * NB + b_own);
        pf_gxz[d] = __ldcg(gx + (size_t)(256 + hcol) * NB + b_own);
        pf_gxn[d] = __ldcg(gx + (size_t)(512 + hcol) * NB + b_own);
        if (d == 0) pf_md[0] = *(const int4*)(D + 0 * NB + rowbase);
        else        pf_md[1] = make_int4(0, 0, 0, 0);
    }

    for (int s = 0; s < SEQ; s++) {
        const int p = s & 1;
#pragma unroll
        for (int d = 0; d < 2; d++) {
            const int t = d ? (SEQ - 1 - s) : s;
            const float* hr = g_h[d][p];
            float* hw = g_h[d][1 - p];

            // lane0 polls: h of step s-1 ready (64 warp arrivals/step); gx slot s+1 ready
            if (lane == 0) {
                if (s) {
                    const unsigned htgt = 64u * (unsigned)s;
                    while (ldAcquire(barp[d]) < htgt) { }
                }
                if (s + 1 < SEQ) {
                    const unsigned q2 = 2u * (unsigned)(s + 1) + (unsigned)d;
                    while (ldAcquire(&g_cnt[q2]) < 12u) { }
                }
            }
            __syncwarp();

            const float4 hscv = make_float4(1.f - (float)pf_md[d].x, 1.f - (float)pf_md[d].y,
                                            1.f - (float)pf_md[d].z, 1.f - (float)pf_md[d].w);

            // load masked h: hreg[e][i] = chunk (i^myrb) of row (rowbase + (myrb^e))
            u64 hreg[4][4][2];
#pragma unroll
            for (int e = 0; e < 4; e++) {
                const int re = myrb ^ e;
                const float hs = pick4(hscv, re);
                const u64 hs2 = pack2(hs, hs);
                const float* rowp = hr + (size_t)(rowbase + re) * HD + kc * 16;
#pragma unroll
                for (int i = 0; i < 4; i++) {
                    const int c = i ^ myrb;
                    float4 v = __ldcg((const float4*)(rowp + c * 4));
                    hreg[e][i][0] = fmul2(pack2(v.x, v.y), hs2);
                    hreg[e][i][1] = fmul2(pack2(v.z, v.w), hs2);
                }
            }
            const float gxr = pf_gxr[d], gxz = pf_gxz[d], gxn = pf_gxn[d];
            const float hself = my_h[d] * pick4(hscv, myrb);

            // prefetch s+1 for this dir (slot already released; loads overlap compute)
            if (s + 1 < SEQ) {
                const int t2 = d ? (SEQ - 2 - s) : (s + 1);
                const float* gx2 = g_gx + ((size_t)d * SEQ + t2) * ((size_t)G3 * NB);
                pf_gxr[d] = __ldcg(gx2 + (size_t)hcol * NB + b_own);
                pf_gxz[d] = __ldcg(gx2 + (size_t)(256 + hcol) * NB + b_own);
                pf_gxn[d] = __ldcg(gx2 + (size_t)(512 + hcol) * NB + b_own);
                if (d == 0) pf_md[0] = *(const int4*)(D + t2 * NB + rowbase);
                else        pf_md[1] = (t2 == SEQ - 1) ? make_int4(0, 0, 0, 0)
                                                       : *(const int4*)(D + (t2 + 1) * NB + rowbase);
            }

            // gate-outer matvec: 16 live accumulators
            float gh[3];
            const float* wkb = Ws + (d * 96 + jg * 4) * SW + kc * 16;
#pragma unroll
            for (int g = 0; g < 3; g++) {
                u64 acc2[16];
#pragma unroll
                for (int dd = 0; dd < 16; dd++) acc2[dd] = 0ull;
#pragma unroll
                for (int i = 0; i < 4; i++) {
                    const int koff = (i ^ myrb) * 4;
#pragma unroll
                    for (int dq = 0; dq < 4; dq++) {
                        const ulonglong2 w2 =
                            *(const ulonglong2*)(wkb + (g * 32 + (myq ^ dq)) * SW + koff);
#pragma unroll
                        for (int e = 0; e < 4; e++) {
                            acc2[e * 4 + dq] = ffma2(hreg[e][i][0], w2.x, acc2[e * 4 + dq]);
                            acc2[e * 4 + dq] = ffma2(hreg[e][i][1], w2.y, acc2[e * 4 + dq]);
                        }
                    }
                }
                float tg[16];
#pragma unroll
                for (int dd = 0; dd < 16; dd++) {
                    float2 f = unpack2(acc2[dd]);
                    tg[dd] = f.x + f.y;
                }
#pragma unroll
                for (int m = 8; m >= 1; m >>= 1) {
#pragma unroll
                    for (int dd = 0; dd < 8; dd++) {
                        if (dd < m)
                            tg[dd] += __shfl_xor_sync(0xffffffffu, tg[dd + m], m);
                    }
                }
                gh[g] = tg[0];
            }

            const float r = sigmoidf_(gxr + gh[0] + bR[d]);
            const float z = sigmoidf_(gxz + gh[1] + bZ[d]);
            const float n = tanhf_(gxn + r * (gh[2] + bN[d]));
            const float hnew = (1.f - z) * n + z * hself;
            my_h[d] = hnew;

            __stcg(hw + (size_t)b_own * HD + hcol, hnew);
            out[((size_t)t * NB + b_own) * (2 * HD) + d * HD + hcol] = hnew;

            // warp-granular arrival: syncwarp orders lane stores before lane0's release
            __syncwarp();
            if (lane == 0) redAddRelease(barp[d], 1u);
        }
    }
}

// ---------------------------------------------------------------- launch
extern "C" void kernel_launch(void* const* d_in, const int* in_sizes, int n_in,
                              void* d_out, int out_size) {
    (void)in_sizes; (void)n_in; (void)out_size;
    const float* X     = (const float*)d_in[0];
    const int*   D     = (const int*)d_in[1];
    const float* Wih_f = (const float*)d_in[2];
    const float* Whh_f = (const float*)d_in[3];
    const float* bih_f = (const float*)d_in[4];
    const float* bhh_f = (const float*)d_in[5];
    const float* Wih_b = (const float*)d_in[6];
    const float* Whh_b = (const float*)d_in[7];
    const float* bih_b = (const float*)d_in[8];
    const float* bhh_b = (const float*)d_in[9];
    float* out = (float*)d_out;

    static int smem_set = 0;
    if (!smem_set) {
        cudaFuncSetAttribute(fused_kernel, cudaFuncAttributeMaxDynamicSharedMemorySize, SMEM_BYTES);
        smem_set = 1;
    }

    init_kernel<<<16, 256>>>();
    fused_kernel<<<NCTA, 256, SMEM_BYTES>>>(X, D, Wih_f, Whh_f, bih_f, bhh_f,
                                            Wih_b, Whh_b, bih_b, bhh_b, out);
}

// round 13
// speedup vs baseline: 1.8841x; 1.8841x over previous
#include <cuda_runtime.h>
#include <cstdint>

#define SEQ 2048
#define NB  64
#define ID  256
#define HD  256
#define G3  768
#define SW  264            // Ws row stride in floats (conflict-free)
#define NGRU 64
#define NPROD 84
#define NCTA (NGRU + NPROD)
#define SMEM_BYTES (2 * 24 * SW * 4)   // 50688

using u64 = unsigned long long;

// ---------------------------------------------------------------- f32x2 helpers
__device__ __forceinline__ u64 ffma2(u64 a, u64 b, u64 c) {
    u64 d; asm("fma.rn.f32x2 %0, %1, %2, %3;" : "=l"(d) : "l"(a), "l"(b), "l"(c)); return d;
}
__device__ __forceinline__ u64 fmul2(u64 a, u64 b) {
    u64 d; asm("mul.rn.f32x2 %0, %1, %2;" : "=l"(d) : "l"(a), "l"(b)); return d;
}
__device__ __forceinline__ u64 pack2(float lo, float hi) {
    u64 d; asm("mov.b64 %0, {%1, %2};" : "=l"(d) : "f"(lo), "f"(hi)); return d;
}
__device__ __forceinline__ float2 unpack2(u64 v) {
    float2 r; asm("mov.b64 {%0, %1}, %2;" : "=f"(r.x), "=f"(r.y) : "l"(v)); return r;
}

// ---------------------------------------------------------------- sync helpers
__device__ __forceinline__ void redAddRelease(unsigned* p, unsigned v) {
    asm volatile("red.add.release.gpu.global.u32 [%0], %1;" :: "l"(p), "r"(v) : "memory");
}
__device__ __forceinline__ unsigned ldAcquire(const unsigned* p) {
    unsigned v; asm volatile("ld.acquire.gpu.global.u32 %0, [%1];" : "=r"(v) : "l"(p) : "memory"); return v;
}

__device__ __forceinline__ float pick4(float4 v, int r) {
    float lo = (r & 1) ? v.y : v.x;
    float hi = (r & 1) ? v.w : v.z;
    return (r & 2) ? hi : lo;
}

__device__ __forceinline__ float sigmoidf_(float x) { return 1.f / (1.f + __expf(-x)); }
__device__ __forceinline__ float tanhf_(float x) {
    float e = __expf(2.f * x);
    return 1.f - 2.f / (e + 1.f);
}

// 805 MB scratch: [dir][t][gate(768)][b(64)]
__device__ float g_gx[(size_t)2 * SEQ * G3 * NB];
// double-buffered hidden state: [dir][parity][b*HD]
__device__ float g_h[2][2][NB * HD];
// h barriers: [dir][bhalf] monotonic counters (256 warp arrivals/step), 128B apart
__device__ unsigned g_bar[4 * 32];
// gx slot counters: slot q = step*2 + dir; ready when == 12
__device__ unsigned g_cnt[2 * SEQ];

// ---------------------------------------------------------------- init
__global__ void init_kernel() {
    int tid = blockIdx.x * blockDim.x + threadIdx.x;
    int nthr = blockDim.x * gridDim.x;
    float* p = &g_h[0][0][0];
    for (int i = tid; i < 2 * 2 * NB * HD; i += nthr) p[i] = 0.f;
    for (int i = tid; i < 2 * SEQ; i += nthr) g_cnt[i] = 0u;
    if (blockIdx.x == 0 && threadIdx.x < 4 * 32) g_bar[threadIdx.x] = 0u;
}

// ---------------------------------------------------------------- producer role: one gx tile
__device__ void gx_tile(
    float* sp, int dir, int t, int n0,
    const float* __restrict__ X,
    const float* __restrict__ W, const float* __restrict__ bias)
{
    float* As = sp;              // [16][68]
    float* Bs = sp + 1088;       // [16][68]
    float* Cs = sp + 2176;       // [64][68]

    const int tid = threadIdx.x;
    const int ty = tid >> 4, tx = tid & 15;
    const int lr = tid >> 2, lc = (tid & 3) << 2;

    const float* Ab  = X + (size_t)t * (NB * ID) + (size_t)lr * ID + lc;
    const float* Bb2 = W + (size_t)(n0 + lr) * ID + lc;

    u64 acc2[4][2];
#pragma unroll
    for (int i = 0; i < 4; i++) { acc2[i][0] = 0ull; acc2[i][1] = 0ull; }

    for (int k0 = 0; k0 < ID; k0 += 16) {
        float4 a4 = *(const float4*)(Ab + k0);
        float4 b4 = *(const float4*)(Bb2 + k0);
        As[(lc + 0) * 68 + lr] = a4.x; As[(lc + 1) * 68 + lr] = a4.y;
        As[(lc + 2) * 68 + lr] = a4.z; As[(lc + 3) * 68 + lr] = a4.w;
        Bs[(lc + 0) * 68 + lr] = b4.x; Bs[(lc + 1) * 68 + lr] = b4.y;
        Bs[(lc + 2) * 68 + lr] = b4.z; Bs[(lc + 3) * 68 + lr] = b4.w;
        __syncthreads();
#pragma unroll
        for (int k = 0; k < 16; k++) {
            float4 av = *(const float4*)&As[k * 68 + (ty << 2)];
            float4 bv = *(const float4*)&Bs[k * 68 + (tx << 2)];
            const u64 b01 = pack2(bv.x, bv.y);
            const u64 b23 = pack2(bv.z, bv.w);
            float ar[4] = {av.x, av.y, av.z, av.w};
#pragma unroll
            for (int r = 0; r < 4; r++) {
                const u64 aa = pack2(ar[r], ar[r]);
                acc2[r][0] = ffma2(aa, b01, acc2[r][0]);
                acc2[r][1] = ffma2(aa, b23, acc2[r][1]);
            }
        }
        __syncthreads();
    }

#pragma unroll
    for (int r = 0; r < 4; r++) {
        float2 c01 = unpack2(acc2[r][0]);
        float2 c23 = unpack2(acc2[r][1]);
        float cc[4] = {c01.x, c01.y, c23.x, c23.y};
#pragma unroll
        for (int c = 0; c < 4; c++)
            Cs[((tx << 2) + c) * 68 + (ty << 2) + r] = cc[c] + __ldg(bias + n0 + (tx << 2) + c);
    }
    __syncthreads();

    float* dst = g_gx + ((size_t)dir * SEQ + t) * ((size_t)G3 * NB) + (size_t)n0 * NB;
#pragma unroll
    for (int i = 0; i < 4; i++) {
        int g  = (tid >> 4) + (i << 4);
        int b4 = (tid & 15) << 2;
        float4 v = *(const float4*)&Cs[g * 68 + b4];
        __stcg((float4*)(dst + g * NB + b4), v);
    }
    __syncthreads();   // all stores done before tid0 releases the slot
}

// ---------------------------------------------------------------- fused persistent kernel
__global__ __launch_bounds__(256, 1) void fused_kernel(
    const float* __restrict__ X,
    const int*   __restrict__ D,
    const float* __restrict__ Wihf, const float* __restrict__ Whf,
    const float* __restrict__ bif,  const float* __restrict__ bhf,
    const float* __restrict__ Wihb, const float* __restrict__ Whb,
    const float* __restrict__ bib,  const float* __restrict__ bhb,
    float* __restrict__ out)
{
    extern __shared__ __align__(16) float sp[];
    const int tid = threadIdx.x;

    if (blockIdx.x >= NGRU) {
        // ================= producer role: gx tiles in consumption-priority order
        const int w = blockIdx.x - NGRU;
        for (int j = w; j < 2 * SEQ * 12; j += NPROD) {
            const int q   = j / 12;
            const int n0  = (j - q * 12) << 6;
            const int dir = q & 1;
            const int st  = q >> 1;
            const int t   = dir ? (SEQ - 1 - st) : st;
            if (dir) gx_tile(sp, 1, t, n0, X, Wihb, bib);
            else     gx_tile(sp, 0, t, n0, X, Wihf, bif);
            if (tid == 0) redAddRelease(&g_cnt[q], 1u);
        }
        return;
    }

    // ================= gru role: R10 partition — bhalf x 8 hcols, both dirs/CTA
    const int bid   = blockIdx.x;
    const int bhalf = bid >> 5;
    const int hc0   = (bid & 31) << 3;
    unsigned* barp[2] = { &g_bar[(0 * 2 + bhalf) * 32], &g_bar[(1 * 2 + bhalf) * 32] };

    float* Ws = sp;   // [dir][24][SW]
    for (int idx = tid; idx < 2 * 24 * 256; idx += 256) {
        int d = idx / (24 * 256);
        int r = (idx >> 8) % 24, k = idx & 255;
        int g = r >> 3, hl = r & 7;
        const float* Whh = d ? Whb : Whf;
        Ws[(d * 24 + r) * SW + k] = Whh[(size_t)(g * 256 + hc0 + hl) * HD + k];
    }

    const int lane = tid & 31;
    const int jg   = tid >> 7;
    const int bl8  = (tid >> 4) & 7;
    const int kc   = tid & 15;
    const int myq  = kc & 3;
    const int myrb = kc >> 2;
    const int rowbase = bhalf * 32 + bl8 * 4;
    const int b_own   = rowbase + myrb;
    const int hcol    = hc0 + jg * 4 + myq;

    float bR[2], bZ[2], bN[2];
#pragma unroll
    for (int d = 0; d < 2; d++) {
        const float* bhh = d ? bhb : bhf;
        bR[d] = __ldg(bhh + hcol);
        bZ[d] = __ldg(bhh + 256 + hcol);
        bN[d] = __ldg(bhh + 512 + hcol);
    }

    __syncthreads();   // Ws ready (one-time)

    float my_h[2] = {0.f, 0.f};
    float pf_gxr[2], pf_gxz[2], pf_gxn[2];
    int4  pf_md[2];

    // wait for step-0 slots of both dirs (lane0 poll + syncwarp), then prefetch
    if (lane == 0) {
        while (ldAcquire(&g_cnt[0]) < 12u) { }
        while (ldAcquire(&g_cnt[1]) < 12u) { }
    }
    __syncwarp();
#pragma unroll
    for (int d = 0; d < 2; d++) {
        const int t0 = d ? (SEQ - 1) : 0;
        const float* gx = g_gx + ((size_t)d * SEQ + t0) * ((size_t)G3 * NB);
        pf_gxr[d] = __ldcg(gx + (size_t)hcol * NB + b_own);
        pf_gxz[d] = __ldcg(gx + (size_t)(256 + hcol) * NB + b_own);
        pf_gxn[d] = __ldcg(gx + (size_t)(512 + hcol) * NB + b_own);
        if (d == 0) pf_md[0] = *(const int4*)(D + 0 * NB + rowbase);
        else        pf_md[1] = make_int4(0, 0, 0, 0);
    }

    for (int s = 0; s < SEQ; s++) {
        const int p = s & 1;
#pragma unroll
        for (int d = 0; d < 2; d++) {
            const int t = d ? (SEQ - 1 - s) : s;
            const float* hr = g_h[d][p];
            float* hw = g_h[d][1 - p];

            // lane0 poll: h of step s-1 ready (256 warp arrivals per step)
            if (s) {
                if (lane == 0) {
                    const unsigned htgt = 256u * (unsigned)s;
                    while (ldAcquire(barp[d]) < htgt) { }
                }
                __syncwarp();
            }

            const float4 hscv = make_float4(1.f - (float)pf_md[d].x, 1.f - (float)pf_md[d].y,
                                            1.f - (float)pf_md[d].z, 1.f - (float)pf_md[d].w);
            const float gxr = pf_gxr[d], gxz = pf_gxz[d], gxn = pf_gxn[d];

            // h loads issue FIRST (critical path), masked-scaled into registers
            u64 hreg[4][4][2];
#pragma unroll
            for (int e = 0; e < 4; e++) {
                const int re = myrb ^ e;
                const float hs = pick4(hscv, re);
                const u64 hs2 = pack2(hs, hs);
                const float* rowp = hr + (size_t)(rowbase + re) * HD + kc * 16;
#pragma unroll
                for (int i = 0; i < 4; i++) {
                    const int c = i ^ myrb;
                    float4 v = __ldcg((const float4*)(rowp + c * 4));
                    hreg[e][i][0] = fmul2(pack2(v.x, v.y), hs2);
                    hreg[e][i][1] = fmul2(pack2(v.z, v.w), hs2);
                }
            }
            const float hself = my_h[d] * pick4(hscv, myrb);

            // gx prefetch for s+1 AFTER h loads (its poll/loads hide under FMA)
            if (s + 1 < SEQ) {
                if (lane == 0) {
                    const unsigned q2 = 2u * (unsigned)(s + 1) + (unsigned)d;
                    while (ldAcquire(&g_cnt[q2]) < 12u) { }
                }
                __syncwarp();
                const int t2 = d ? (SEQ - 2 - s) : (s + 1);
                const float* gx2 = g_gx + ((size_t)d * SEQ + t2) * ((size_t)G3 * NB);
                pf_gxr[d] = __ldcg(gx2 + (size_t)hcol * NB + b_own);
                pf_gxz[d] = __ldcg(gx2 + (size_t)(256 + hcol) * NB + b_own);
                pf_gxn[d] = __ldcg(gx2 + (size_t)(512 + hcol) * NB + b_own);
                if (d == 0) pf_md[0] = *(const int4*)(D + t2 * NB + rowbase);
                else        pf_md[1] = (t2 == SEQ - 1) ? make_int4(0, 0, 0, 0)
                                                       : *(const int4*)(D + (t2 + 1) * NB + rowbase);
            }

            // gate-outer matvec: 16 live accumulators (no spills)
            float gh[3];
            const float* wkb = Ws + (d * 24 + jg * 4) * SW + kc * 16;
#pragma unroll
            for (int g = 0; g < 3; g++) {
                u64 acc2[16];
#pragma unroll
                for (int dd = 0; dd < 16; dd++) acc2[dd] = 0ull;
#pragma unroll
                for (int i = 0; i < 4; i++) {
                    const int koff = (i ^ myrb) * 4;
#pragma unroll
                    for (int dq = 0; dq < 4; dq++) {
                        const ulonglong2 w2 = *(const ulonglong2*)(wkb + (g * 8 + (myq ^ dq)) * SW + koff);
#pragma unroll
                        for (int e = 0; e < 4; e++) {
                            acc2[e * 4 + dq] = ffma2(hreg[e][i][0], w2.x, acc2[e * 4 + dq]);
                            acc2[e * 4 + dq] = ffma2(hreg[e][i][1], w2.y, acc2[e * 4 + dq]);
                        }
                    }
                }
                float tg[16];
#pragma unroll
                for (int dd = 0; dd < 16; dd++) {
                    float2 f = unpack2(acc2[dd]);
                    tg[dd] = f.x + f.y;
                }
#pragma unroll
                for (int m = 8; m >= 1; m >>= 1) {
#pragma unroll
                    for (int dd = 0; dd < 8; dd++) {
                        if (dd < m)
                            tg[dd] += __shfl_xor_sync(0xffffffffu, tg[dd + m], m);
                    }
                }
                gh[g] = tg[0];
            }

            const float r = sigmoidf_(gxr + gh[0] + bR[d]);
            const float z = sigmoidf_(gxz + gh[1] + bZ[d]);
            const float n = tanhf_(gxn + r * (gh[2] + bN[d]));
            const float hnew = (1.f - z) * n + z * hself;
            my_h[d] = hnew;

            __stcg(hw + (size_t)b_own * HD + hcol, hnew);
            out[((size_t)t * NB + b_own) * (2 * HD) + d * HD + hcol] = hnew;

            // warp-granular arrival: syncwarp orders lane stores before lane0's release
            __syncwarp();
            if (lane == 0) redAddRelease(barp[d], 1u);
        }
    }
}

// ---------------------------------------------------------------- launch
extern "C" void kernel_launch(void* const* d_in, const int* in_sizes, int n_in,
                              void* d_out, int out_size) {
    (void)in_sizes; (void)n_in; (void)out_size;
    const float* X     = (const float*)d_in[0];
    const int*   D     = (const int*)d_in[1];
    const float* Wih_f = (const float*)d_in[2];
    const float* Whh_f = (const float*)d_in[3];
    const float* bih_f = (const float*)d_in[4];
    const float* bhh_f = (const float*)d_in[5];
    const float* Wih_b = (const float*)d_in[6];
    const float* Whh_b = (const float*)d_in[7];
    const float* bih_b = (const float*)d_in[8];
    const float* bhh_b = (const float*)d_in[9];
    float* out = (float*)d_out;

    static int smem_set = 0;
    if (!smem_set) {
        cudaFuncSetAttribute(fused_kernel, cudaFuncAttributeMaxDynamicSharedMemorySize, SMEM_BYTES);
        smem_set = 1;
    }

    init_kernel<<<16, 256>>>();
    fused_kernel<<<NCTA, 256, SMEM_BYTES>>>(X, D, Wih_f, Whh_f, bih_f, bhh_f,
                                            Wih_b, Whh_b, bih_b, bhh_b, out);
}